// round 9
// baseline (speedup 1.0000x reference)
#include <cuda_runtime.h>
#include <cstdint>

typedef unsigned long long ull;

#define SLEN 1024
#define BSZ  32
#define IND  512
#define NH   8
#define HD   64
#define NQKV 1544              // H*(3*D+1)
#define MROWS (SLEN*BSZ)       // 32768
#define NPAIR (BSZ*NH)         // 256

// ---------------- scratch (device globals; no allocation allowed) ----------
__device__ float g_h[(size_t)MROWS*IND];
__device__ float g_qkvb[(size_t)MROWS*NQKV];
__device__ float g_q[(size_t)NPAIR*SLEN*HD];   // [bh][t][d]
__device__ float g_k[(size_t)NPAIR*SLEN*HD];
__device__ float g_v[(size_t)NPAIR*SLEN*HD];
__device__ float g_beta[(size_t)NPAIR*SLEN];
__device__ float g_o[(size_t)MROWS*IND];
__device__ float g_wsr[(size_t)IND*NQKV];
__device__ float g_wor[(size_t)IND*IND];

// ---------------- helpers --------------------------------------------------
__device__ __forceinline__ float tf32f(float f) {
    uint32_t u;
    asm("cvt.rna.tf32.f32 %0, %1;" : "=r"(u) : "f"(f));
    return __uint_as_float(u);
}
__device__ __forceinline__ uint32_t smem_u32(const void* p) {
    return (uint32_t)__cvta_generic_to_shared(p);
}
__device__ __forceinline__ void cp4(uint32_t d, const void* s) {
    asm volatile("cp.async.ca.shared.global [%0], [%1], 4;\n" :: "r"(d), "l"(s));
}
__device__ __forceinline__ void cp16(uint32_t d, const void* s) {
    asm volatile("cp.async.cg.shared.global [%0], [%1], 16;\n" :: "r"(d), "l"(s));
}
__device__ __forceinline__ void cp16z(uint32_t d, const void* s, int sz) {
    asm volatile("cp.async.cg.shared.global [%0], [%1], 16, %2;\n"
                 :: "r"(d), "l"(s), "r"(sz));
}
#define CP_COMMIT() asm volatile("cp.async.commit_group;\n" ::: "memory")
#define CP_WAIT1()  asm volatile("cp.async.wait_group 1;\n" ::: "memory")

__device__ __forceinline__ void mma_tf32(float* c, const uint32_t* a, const uint32_t* b) {
    asm volatile(
        "mma.sync.aligned.m16n8k8.row.col.f32.tf32.tf32.f32 "
        "{%0,%1,%2,%3},{%4,%5,%6,%7},{%8,%9},{%0,%1,%2,%3};\n"
        : "+f"(c[0]), "+f"(c[1]), "+f"(c[2]), "+f"(c[3])
        : "r"(a[0]), "r"(a[1]), "r"(a[2]), "r"(a[3]), "r"(b[0]), "r"(b[1]));
}

__device__ __forceinline__ ull fma2(ull a, ull b, ull c) {
    ull d; asm("fma.rn.f32x2 %0,%1,%2,%3;" : "=l"(d) : "l"(a), "l"(b), "l"(c)); return d;
}
__device__ __forceinline__ ull pack2(float x, float y) {
    ull r; asm("mov.b64 %0,{%1,%2};" : "=l"(r) : "f"(x), "f"(y)); return r;
}
__device__ __forceinline__ float hsum2(ull a) {
    float x, y; asm("mov.b64 {%0,%1},%2;" : "=f"(x), "=f"(y) : "l"(a)); return x + y;
}

// ---------------- weight rounding (both weight matrices, one launch) -------
__global__ void round_w_kernel(const float* __restrict__ s1, float* __restrict__ d1, int n1,
                               const float* __restrict__ s2, float* __restrict__ d2, int n2) {
    int stride = gridDim.x * 256;
    for (int i = blockIdx.x * 256 + threadIdx.x; i < n1 + n2; i += stride) {
        if (i < n1) d1[i] = tf32f(s1[i]);
        else        d2[i - n1] = tf32f(s2[i - n1]);
    }
}

// ---------------- layernorm ------------------------------------------------
__global__ __launch_bounds__(256) void ln_kernel(
    const float* __restrict__ x, const float* __restrict__ gam,
    const float* __restrict__ bet, float* __restrict__ h)
{
    int row  = blockIdx.x * 8 + (threadIdx.x >> 5);
    int lane = threadIdx.x & 31;
    const float4* xr = (const float4*)(x + (size_t)row * IND);
    float4 v[4];
    float s = 0.f, s2 = 0.f;
#pragma unroll
    for (int i = 0; i < 4; i++) {
        v[i] = xr[lane + i * 32];
        s  += v[i].x + v[i].y + v[i].z + v[i].w;
        s2 += v[i].x*v[i].x + v[i].y*v[i].y + v[i].z*v[i].z + v[i].w*v[i].w;
    }
#pragma unroll
    for (int o = 16; o; o >>= 1) {
        s  += __shfl_xor_sync(0xffffffffu, s,  o);
        s2 += __shfl_xor_sync(0xffffffffu, s2, o);
    }
    float mu  = s * (1.f / IND);
    float var = s2 * (1.f / IND) - mu * mu;
    float ri  = rsqrtf(var + 1e-5f);
    const float4* gr = (const float4*)gam;
    const float4* br = (const float4*)bet;
    float4* hr = (float4*)(h + (size_t)row * IND);
#pragma unroll
    for (int i = 0; i < 4; i++) {
        int c = lane + i * 32;
        float4 g4 = gr[c], b4 = br[c], o4;
        o4.x = tf32f((v[i].x - mu) * ri * g4.x + b4.x);
        o4.y = tf32f((v[i].y - mu) * ri * g4.y + b4.y);
        o4.z = tf32f((v[i].z - mu) * ri * g4.z + b4.z);
        o4.w = tf32f((v[i].w - mu) * ri * g4.w + b4.w);
        hr[c] = o4;
    }
}

// ---------------- tf32 GEMM: C[M,N] = A[M,K] @ B[K,N] (+R) -----------------
#define BM 128
#define BN 64
#define BK 16
#define ASTR 20
#define BSTR 72

template<bool RES>
__global__ __launch_bounds__(256) void gemm_tf32(
    const float* __restrict__ A, const float* __restrict__ B,
    float* __restrict__ C, const float* __restrict__ R,
    int M, int N, int K)
{
    __shared__ __align__(16) float As[3][BM * ASTR];
    __shared__ __align__(16) float Bs[3][BK * BSTR];
    int tid = threadIdx.x, warp = tid >> 5, lane = tid & 31;
    int wm = warp >> 1, wn = warp & 1;
    int m0 = blockIdx.y * BM, n0 = blockIdx.x * BN;

    float acc[2][4][4];
#pragma unroll
    for (int a = 0; a < 2; a++)
#pragma unroll
        for (int b = 0; b < 4; b++)
#pragma unroll
            for (int c = 0; c < 4; c++) acc[a][b][c] = 0.f;

    auto loadA = [&](int s, int k0) {
#pragma unroll
        for (int i = 0; i < 2; i++) {
            int idx = tid + i * 256;
            int row = idx >> 2, kc = (idx & 3) * 4;
            cp16(smem_u32(&As[s][row * ASTR + kc]),
                 A + (size_t)(m0 + row) * K + k0 + kc);
        }
    };
    auto loadB = [&](int s, int k0) {
        int row = tid >> 4, nc = (tid & 15) * 4;
        int col = n0 + nc;
        const float* src = (col < N) ? (B + (size_t)(k0 + row) * N + col) : B;
        cp16z(smem_u32(&Bs[s][row * BSTR + nc]), src, (col < N) ? 16 : 0);
    };

    int KT = K / BK;
    loadA(0, 0);  loadB(0, 0);  CP_COMMIT();
    loadA(1, BK); loadB(1, BK); CP_COMMIT();

    for (int kt = 0; kt < KT; kt++) {
        CP_WAIT1();
        __syncthreads();
        int kn = kt + 2;
        if (kn < KT) { loadA(kn % 3, kn * BK); loadB(kn % 3, kn * BK); }
        CP_COMMIT();

        int s = kt % 3;
#pragma unroll
        for (int kk = 0; kk < BK; kk += 8) {
            uint32_t af[2][4], bf[4][2];
#pragma unroll
            for (int mi = 0; mi < 2; mi++) {
                const float* p = &As[s][(wm * 32 + mi * 16 + (lane >> 2)) * ASTR + kk + (lane & 3)];
                af[mi][0] = __float_as_uint(p[0]);
                af[mi][1] = __float_as_uint(p[8 * ASTR]);
                af[mi][2] = __float_as_uint(p[4]);
                af[mi][3] = __float_as_uint(p[8 * ASTR + 4]);
            }
#pragma unroll
            for (int ni = 0; ni < 4; ni++) {
                const float* p = &Bs[s][(kk + (lane & 3)) * BSTR + wn * 32 + ni * 8 + (lane >> 2)];
                bf[ni][0] = __float_as_uint(p[0]);
                bf[ni][1] = __float_as_uint(p[4 * BSTR]);
            }
#pragma unroll
            for (int mi = 0; mi < 2; mi++)
#pragma unroll
                for (int ni = 0; ni < 4; ni++)
                    mma_tf32(acc[mi][ni], af[mi], bf[ni]);
        }
    }

#pragma unroll
    for (int mi = 0; mi < 2; mi++)
#pragma unroll
        for (int ni = 0; ni < 4; ni++) {
            int row = m0 + wm * 32 + mi * 16 + (lane >> 2);
            int col = n0 + wn * 32 + ni * 8 + (lane & 3) * 2;
            if (col < N) {
                size_t i0 = (size_t)row * N + col;
                size_t i1 = (size_t)(row + 8) * N + col;
                const float* c4 = acc[mi][ni];
                float2 r0, r1;
                if (RES) {
                    r0.x = c4[0] + R[i0]; r0.y = c4[1] + R[i0 + 1];
                    r1.x = c4[2] + R[i1]; r1.y = c4[3] + R[i1 + 1];
                } else {
                    r0.x = c4[0]; r0.y = c4[1];
                    r1.x = c4[2]; r1.y = c4[3];
                }
                *(float2*)(C + i0) = r0;
                *(float2*)(C + i1) = r1;
            }
        }
}

// ---------------- activation / transpose prep ------------------------------
__device__ __forceinline__ float elu1(float x) {
    return x > 0.f ? x + 1.f : __expf(x);
}

__global__ __launch_bounds__(256) void prep_kernel(
    const float* __restrict__ qkvb, float* __restrict__ q, float* __restrict__ k,
    float* __restrict__ v, float* __restrict__ be)
{
    int gw   = blockIdx.x * 8 + (threadIdx.x >> 5);
    int lane = threadIdx.x & 31;
    int h = gw & 7;
    int r = gw >> 3;          // r = t*32 + b
    int b = r & 31;
    int t = r >> 5;
    const float* base = qkvb + (size_t)r * NQKV + h * 193;
    int bh = b * NH + h;
    size_t od = ((size_t)bh * SLEN + t) * HD + lane;

    // q
    float q0 = elu1(base[lane]), q1 = elu1(base[lane + 32]);
    float s = q0 + q1;
#pragma unroll
    for (int o = 16; o; o >>= 1) s += __shfl_xor_sync(0xffffffffu, s, o);
    float inv = 1.f / s;
    q[od] = q0 * inv; q[od + 32] = q1 * inv;
    // k
    float k0 = elu1(base[64 + lane]), k1 = elu1(base[96 + lane]);
    s = k0 + k1;
#pragma unroll
    for (int o = 16; o; o >>= 1) s += __shfl_xor_sync(0xffffffffu, s, o);
    inv = 1.f / s;
    k[od] = k0 * inv; k[od + 32] = k1 * inv;
    // v
    v[od] = base[128 + lane]; v[od + 32] = base[160 + lane];
    // beta
    if (lane == 0) be[(size_t)bh * SLEN + t] = 1.f / (1.f + __expf(-base[192]));
}

// ---------------- delta-rule recurrence ------------------------------------
#define CH 8
__global__ __launch_bounds__(128) void recur_kernel(
    const float* __restrict__ gq, const float* __restrict__ gk,
    const float* __restrict__ gv, const float* __restrict__ gb,
    float* __restrict__ go)
{
    __shared__ __align__(16) float sq[2][2][CH * HD];
    __shared__ __align__(16) float sk[2][2][CH * HD];
    __shared__ __align__(16) float sv[2][2][CH * HD];
    __shared__ __align__(16) float sb[2][2][CH];

    int tid = threadIdx.x;
    int pl  = tid >> 6;       // pair within block
    int i   = tid & 63;       // owned W row
    int bh0 = blockIdx.x * 2;
    int bh  = bh0 + pl;
    int bb  = bh >> 3, hh = bh & 7;

    ull W[32];
#pragma unroll
    for (int j = 0; j < 32; j++) W[j] = 0ull;

    auto load_chunk = [&](int buf, int t0) {
        int off = tid * 4;
        cp16(smem_u32(&sq[buf][0][off]), gq + ((size_t)(bh0    ) * SLEN + t0) * HD + off);
        cp16(smem_u32(&sq[buf][1][off]), gq + ((size_t)(bh0 + 1) * SLEN + t0) * HD + off);
        cp16(smem_u32(&sk[buf][0][off]), gk + ((size_t)(bh0    ) * SLEN + t0) * HD + off);
        cp16(smem_u32(&sk[buf][1][off]), gk + ((size_t)(bh0 + 1) * SLEN + t0) * HD + off);
        cp16(smem_u32(&sv[buf][0][off]), gv + ((size_t)(bh0    ) * SLEN + t0) * HD + off);
        cp16(smem_u32(&sv[buf][1][off]), gv + ((size_t)(bh0 + 1) * SLEN + t0) * HD + off);
        if (i < CH) cp4(smem_u32(&sb[buf][pl][i]), gb + (size_t)bh * SLEN + t0 + i);
    };

    load_chunk(0, 0);
    CP_COMMIT();
    int NCH = SLEN / CH;
    for (int c = 0; c < NCH; c++) {
        if (c + 1 < NCH) load_chunk((c + 1) & 1, (c + 1) * CH);
        CP_COMMIT();
        CP_WAIT1();
        __syncthreads();
        int buf = c & 1;
        const float* pq = &sq[buf][pl][0];
        const float* pk = &sk[buf][pl][0];
        const float* pv = &sv[buf][pl][0];
        const float* pb = &sb[buf][pl][0];
#pragma unroll
        for (int s = 0; s < CH; s++) {
            ull kc[32];
            const ull* k2 = (const ull*)(pk + s * HD);
#pragma unroll
            for (int j = 0; j < 32; j++) kc[j] = k2[j];
            ull a0 = 0, a1 = 0, a2 = 0, a3 = 0;
#pragma unroll
            for (int j = 0; j < 32; j += 4) {
                a0 = fma2(W[j],     kc[j],     a0);
                a1 = fma2(W[j + 1], kc[j + 1], a1);
                a2 = fma2(W[j + 2], kc[j + 2], a2);
                a3 = fma2(W[j + 3], kc[j + 3], a3);
            }
            float vold = (hsum2(a0) + hsum2(a1)) + (hsum2(a2) + hsum2(a3));
            float vi = pv[s * HD + i];
            float bt = pb[s];
            float u  = bt * (vi - vold);
            ull u2 = pack2(u, u);
#pragma unroll
            for (int j = 0; j < 32; j++) W[j] = fma2(u2, kc[j], W[j]);
            const ull* q2 = (const ull*)(pq + s * HD);
#pragma unroll
            for (int j = 0; j < 32; j++) kc[j] = q2[j];
            a0 = a1 = a2 = a3 = 0;
#pragma unroll
            for (int j = 0; j < 32; j += 4) {
                a0 = fma2(W[j],     kc[j],     a0);
                a1 = fma2(W[j + 1], kc[j + 1], a1);
                a2 = fma2(W[j + 2], kc[j + 2], a2);
                a3 = fma2(W[j + 3], kc[j + 3], a3);
            }
            float oi = (hsum2(a0) + hsum2(a1)) + (hsum2(a2) + hsum2(a3));
            int t = c * CH + s;
            go[((size_t)t * BSZ + bb) * IND + hh * HD + i] = tf32f(oi);
        }
        __syncthreads();
    }
}

// ---------------- launch ----------------------------------------------------
extern "C" void kernel_launch(void* const* d_in, const int* in_sizes, int n_in,
                              void* d_out, int out_size)
{
    const float* x     = (const float*)d_in[0];
    const float* gam   = (const float*)d_in[1];
    const float* bet   = (const float*)d_in[2];
    const float* wslow = (const float*)d_in[3];
    const float* wout  = (const float*)d_in[4];

    float *h, *qkvb, *q, *k, *v, *be, *o, *wsr, *wor;
    cudaGetSymbolAddress((void**)&h,    g_h);
    cudaGetSymbolAddress((void**)&qkvb, g_qkvb);
    cudaGetSymbolAddress((void**)&q,    g_q);
    cudaGetSymbolAddress((void**)&k,    g_k);
    cudaGetSymbolAddress((void**)&v,    g_v);
    cudaGetSymbolAddress((void**)&be,   g_beta);
    cudaGetSymbolAddress((void**)&o,    g_o);
    cudaGetSymbolAddress((void**)&wsr,  g_wsr);
    cudaGetSymbolAddress((void**)&wor,  g_wor);

    round_w_kernel<<<592, 256>>>(wslow, wsr, IND * NQKV, wout, wor, IND * IND);

    ln_kernel<<<MROWS / 8, 256>>>(x, gam, bet, h);

    {
        dim3 grid((NQKV + BN - 1) / BN, MROWS / BM);
        gemm_tf32<false><<<grid, 256>>>(h, wsr, qkvb, nullptr, MROWS, NQKV, IND);
    }

    prep_kernel<<<MROWS * NH / 8, 256>>>(qkvb, q, k, v, be);

    recur_kernel<<<NPAIR / 2, 128>>>(q, k, v, be, o);

    {
        dim3 grid(IND / BN, MROWS / BM);
        gemm_tf32<true><<<grid, 256>>>(o, wor, (float*)d_out, x, MROWS, IND, IND);
    }
}

// round 12
// speedup vs baseline: 1.4988x; 1.4988x over previous
#include <cuda_runtime.h>
#include <cuda_bf16.h>
#include <cstdint>

typedef unsigned long long ull;

#define SLEN 1024
#define BSZ  32
#define IND  512
#define NH   8
#define HD   64
#define NQKV 1544              // H*(3*D+1)
#define MROWS (SLEN*BSZ)       // 32768
#define NPAIR (BSZ*NH)         // 256

// ---------------- scratch (device globals; no allocation allowed) ----------
__device__ __nv_bfloat16 g_h[(size_t)MROWS*IND];
__device__ __nv_bfloat16 g_qkvb[(size_t)MROWS*NQKV];
__device__ float g_q[(size_t)NPAIR*SLEN*HD];   // [bh][t][d] fp32 (recurrence precision)
__device__ float g_k[(size_t)NPAIR*SLEN*HD];
__device__ float g_v[(size_t)NPAIR*SLEN*HD];
__device__ float g_beta[(size_t)NPAIR*SLEN];
__device__ __nv_bfloat16 g_o[(size_t)MROWS*IND];
__device__ __nv_bfloat16 g_wsr[(size_t)IND*NQKV];
__device__ __nv_bfloat16 g_wor[(size_t)IND*IND];

// ---------------- helpers --------------------------------------------------
__device__ __forceinline__ uint32_t smem_u32(const void* p) {
    return (uint32_t)__cvta_generic_to_shared(p);
}
__device__ __forceinline__ void cp4(uint32_t d, const void* s) {
    asm volatile("cp.async.ca.shared.global [%0], [%1], 4;\n" :: "r"(d), "l"(s));
}
__device__ __forceinline__ void cp16(uint32_t d, const void* s) {
    asm volatile("cp.async.cg.shared.global [%0], [%1], 16;\n" :: "r"(d), "l"(s));
}
__device__ __forceinline__ void cp16z(uint32_t d, const void* s, int sz) {
    asm volatile("cp.async.cg.shared.global [%0], [%1], 16, %2;\n"
                 :: "r"(d), "l"(s), "r"(sz));
}
#define CP_COMMIT() asm volatile("cp.async.commit_group;\n" ::: "memory")
#define CP_WAIT1()  asm volatile("cp.async.wait_group 1;\n" ::: "memory")

__device__ __forceinline__ void ldsm_x4(uint32_t* r, uint32_t addr) {
    asm volatile("ldmatrix.sync.aligned.m8n8.x4.shared.b16 {%0,%1,%2,%3}, [%4];"
                 : "=r"(r[0]), "=r"(r[1]), "=r"(r[2]), "=r"(r[3]) : "r"(addr));
}
__device__ __forceinline__ void ldsm_x2t(uint32_t* r, uint32_t addr) {
    asm volatile("ldmatrix.sync.aligned.m8n8.x2.trans.shared.b16 {%0,%1}, [%2];"
                 : "=r"(r[0]), "=r"(r[1]) : "r"(addr));
}
__device__ __forceinline__ void mma_bf16(float* c, const uint32_t* a, const uint32_t* b) {
    asm volatile(
        "mma.sync.aligned.m16n8k16.row.col.f32.bf16.bf16.f32 "
        "{%0,%1,%2,%3},{%4,%5,%6,%7},{%8,%9},{%0,%1,%2,%3};\n"
        : "+f"(c[0]), "+f"(c[1]), "+f"(c[2]), "+f"(c[3])
        : "r"(a[0]), "r"(a[1]), "r"(a[2]), "r"(a[3]), "r"(b[0]), "r"(b[1]));
}

__device__ __forceinline__ ull fma2(ull a, ull b, ull c) {
    ull d; asm("fma.rn.f32x2 %0,%1,%2,%3;" : "=l"(d) : "l"(a), "l"(b), "l"(c)); return d;
}
__device__ __forceinline__ ull pack2(float x, float y) {
    ull r; asm("mov.b64 %0,{%1,%2};" : "=l"(r) : "f"(x), "f"(y)); return r;
}
__device__ __forceinline__ float hsum2(ull a) {
    float x, y; asm("mov.b64 {%0,%1},%2;" : "=f"(x), "=f"(y) : "l"(a)); return x + y;
}

// ---------------- weight rounding to bf16 (both matrices, one launch) ------
__global__ void round_w_kernel(const float* __restrict__ s1, __nv_bfloat16* __restrict__ d1, int n1,
                               const float* __restrict__ s2, __nv_bfloat16* __restrict__ d2, int n2) {
    int stride = gridDim.x * 256;
    for (int i = blockIdx.x * 256 + threadIdx.x; i < n1 + n2; i += stride) {
        if (i < n1) d1[i] = __float2bfloat16_rn(s1[i]);
        else        d2[i - n1] = __float2bfloat16_rn(s2[i - n1]);
    }
}

// ---------------- layernorm (fp32 in, bf16 out) ----------------------------
__global__ __launch_bounds__(256) void ln_kernel(
    const float* __restrict__ x, const float* __restrict__ gam,
    const float* __restrict__ bet, __nv_bfloat16* __restrict__ h)
{
    int row  = blockIdx.x * 8 + (threadIdx.x >> 5);
    int lane = threadIdx.x & 31;
    const float4* xr = (const float4*)(x + (size_t)row * IND);
    float4 v[4];
    float s = 0.f, s2 = 0.f;
#pragma unroll
    for (int i = 0; i < 4; i++) {
        v[i] = xr[lane + i * 32];
        s  += v[i].x + v[i].y + v[i].z + v[i].w;
        s2 += v[i].x*v[i].x + v[i].y*v[i].y + v[i].z*v[i].z + v[i].w*v[i].w;
    }
#pragma unroll
    for (int o = 16; o; o >>= 1) {
        s  += __shfl_xor_sync(0xffffffffu, s,  o);
        s2 += __shfl_xor_sync(0xffffffffu, s2, o);
    }
    float mu  = s * (1.f / IND);
    float var = s2 * (1.f / IND) - mu * mu;
    float ri  = rsqrtf(var + 1e-5f);
    const float4* gr = (const float4*)gam;
    const float4* br = (const float4*)bet;
    uint2* hr = (uint2*)(h + (size_t)row * IND);   // 4 bf16 per uint2
#pragma unroll
    for (int i = 0; i < 4; i++) {
        int c = lane + i * 32;
        float4 g4 = gr[c], b4 = br[c];
        __nv_bfloat162 lo = __floats2bfloat162_rn((v[i].x - mu) * ri * g4.x + b4.x,
                                                  (v[i].y - mu) * ri * g4.y + b4.y);
        __nv_bfloat162 hi = __floats2bfloat162_rn((v[i].z - mu) * ri * g4.z + b4.z,
                                                  (v[i].w - mu) * ri * g4.w + b4.w);
        uint2 o4;
        o4.x = *(uint32_t*)&lo;
        o4.y = *(uint32_t*)&hi;
        hr[c] = o4;
    }
}

// ---------------- bf16 GEMM: C[M,N] = A[M,K] @ B[K,N] (+R) -----------------
// RES=false: C is bf16. RES=true: C is fp32 with fp32 residual R added.
#define BM 128
#define BN 64
#define BK 32          // bf16 elements per K-tile (2 x k16 MMA steps)
#define ASTR 40        // bf16 per A row (80B = 5 x 16B chunks -> ldmatrix conflict-free)
#define BSTR 72        // bf16 per B row (144B = 9 chunks == 1 mod 8 -> conflict-free)

template<bool RES>
__global__ __launch_bounds__(256) void gemm_bf16(
    const __nv_bfloat16* __restrict__ A, const __nv_bfloat16* __restrict__ B,
    void* __restrict__ Cout, const float* __restrict__ R,
    int M, int N, int K)
{
    __shared__ __align__(16) __nv_bfloat16 As[3][BM * ASTR];
    __shared__ __align__(16) __nv_bfloat16 Bs[3][BK * BSTR];
    int tid = threadIdx.x, warp = tid >> 5, lane = tid & 31;
    int wm = warp >> 1, wn = warp & 1;          // 4 x 2 warp grid; warp tile 32m x 32n
    int m0 = blockIdx.y * BM, n0 = blockIdx.x * BN;
    int lr = lane & 7, sel = lane >> 3;         // ldmatrix address lanes

    float acc[2][4][4];
#pragma unroll
    for (int a = 0; a < 2; a++)
#pragma unroll
        for (int b = 0; b < 4; b++)
#pragma unroll
            for (int c = 0; c < 4; c++) acc[a][b][c] = 0.f;

    auto loadA = [&](int s, int k0) {
#pragma unroll
        for (int i = 0; i < 2; i++) {
            int idx = tid + i * 256;
            int row = idx >> 2, kc = (idx & 3) * 8;     // 8 bf16 = 16B chunk
            cp16(smem_u32(&As[s][row * ASTR + kc]),
                 A + (size_t)(m0 + row) * K + k0 + kc);
        }
    };
    auto loadB = [&](int s, int k0) {
        int row = tid >> 3, nc = (tid & 7) * 8;
        int col = n0 + nc;
        const __nv_bfloat16* src = (col < N) ? (B + (size_t)(k0 + row) * N + col) : B;
        cp16z(smem_u32(&Bs[s][row * BSTR + nc]), src, (col < N) ? 16 : 0);
    };

    int KT = K / BK;
    loadA(0, 0);  loadB(0, 0);  CP_COMMIT();
    loadA(1, BK); loadB(1, BK); CP_COMMIT();

    for (int kt = 0; kt < KT; kt++) {
        CP_WAIT1();
        __syncthreads();
        int kn = kt + 2;
        if (kn < KT) { loadA(kn % 3, kn * BK); loadB(kn % 3, kn * BK); }
        CP_COMMIT();

        int s = kt % 3;
#pragma unroll
        for (int kk = 0; kk < BK; kk += 16) {
            uint32_t af[2][4], bfr[4][2];
#pragma unroll
            for (int mi = 0; mi < 2; mi++) {
                int arow = wm * 32 + mi * 16 + ((sel & 1) << 3) + lr;
                int acol = kk + ((sel >> 1) << 3);
                ldsm_x4(af[mi], smem_u32(&As[s][arow * ASTR + acol]));
            }
#pragma unroll
            for (int ni = 0; ni < 4; ni++) {
                int brow = kk + ((sel & 1) << 3) + lr;
                ldsm_x2t(bfr[ni], smem_u32(&Bs[s][brow * BSTR + wn * 32 + ni * 8]));
            }
#pragma unroll
            for (int mi = 0; mi < 2; mi++)
#pragma unroll
                for (int ni = 0; ni < 4; ni++)
                    mma_bf16(acc[mi][ni], af[mi], bfr[ni]);
        }
    }

#pragma unroll
    for (int mi = 0; mi < 2; mi++)
#pragma unroll
        for (int ni = 0; ni < 4; ni++) {
            int row = m0 + wm * 32 + mi * 16 + (lane >> 2);
            int col = n0 + wn * 32 + ni * 8 + (lane & 3) * 2;
            if (col < N) {
                size_t i0 = (size_t)row * N + col;
                size_t i1 = (size_t)(row + 8) * N + col;
                const float* c4 = acc[mi][ni];
                if (RES) {
                    float* C = (float*)Cout;
                    float2 r0, r1;
                    r0.x = c4[0] + R[i0]; r0.y = c4[1] + R[i0 + 1];
                    r1.x = c4[2] + R[i1]; r1.y = c4[3] + R[i1 + 1];
                    *(float2*)(C + i0) = r0;
                    *(float2*)(C + i1) = r1;
                } else {
                    __nv_bfloat16* C = (__nv_bfloat16*)Cout;
                    __nv_bfloat162 p0 = __floats2bfloat162_rn(c4[0], c4[1]);
                    __nv_bfloat162 p1 = __floats2bfloat162_rn(c4[2], c4[3]);
                    *(__nv_bfloat162*)(C + i0) = p0;
                    *(__nv_bfloat162*)(C + i1) = p1;
                }
            }
        }
}

// ---------------- activation / transpose prep (bf16 in, fp32 out) ----------
__device__ __forceinline__ float elu1(float x) {
    return x > 0.f ? x + 1.f : __expf(x);
}

__global__ __launch_bounds__(256) void prep_kernel(
    const __nv_bfloat16* __restrict__ qkvb, float* __restrict__ q, float* __restrict__ k,
    float* __restrict__ v, float* __restrict__ be)
{
    int gw   = blockIdx.x * 8 + (threadIdx.x >> 5);
    int lane = threadIdx.x & 31;
    int h = gw & 7;
    int r = gw >> 3;          // r = t*32 + b
    int b = r & 31;
    int t = r >> 5;
    const __nv_bfloat16* base = qkvb + (size_t)r * NQKV + h * 193;
    int bh = b * NH + h;
    size_t od = ((size_t)bh * SLEN + t) * HD + lane;

    // q
    float q0 = elu1(__bfloat162float(base[lane]));
    float q1 = elu1(__bfloat162float(base[lane + 32]));
    float s = q0 + q1;
#pragma unroll
    for (int o = 16; o; o >>= 1) s += __shfl_xor_sync(0xffffffffu, s, o);
    float inv = 1.f / s;
    q[od] = q0 * inv; q[od + 32] = q1 * inv;
    // k
    float k0 = elu1(__bfloat162float(base[64 + lane]));
    float k1 = elu1(__bfloat162float(base[96 + lane]));
    s = k0 + k1;
#pragma unroll
    for (int o = 16; o; o >>= 1) s += __shfl_xor_sync(0xffffffffu, s, o);
    inv = 1.f / s;
    k[od] = k0 * inv; k[od + 32] = k1 * inv;
    // v
    v[od]      = __bfloat162float(base[128 + lane]);
    v[od + 32] = __bfloat162float(base[160 + lane]);
    // beta
    if (lane == 0) be[(size_t)bh * SLEN + t] = 1.f / (1.f + __expf(-__bfloat162float(base[192])));
}

// ---------------- delta-rule recurrence (fp32, bf16 output) -----------------
#define CH 8
__global__ __launch_bounds__(128) void recur_kernel(
    const float* __restrict__ gq, const float* __restrict__ gk,
    const float* __restrict__ gv, const float* __restrict__ gb,
    __nv_bfloat16* __restrict__ go)
{
    __shared__ __align__(16) float sq[2][2][CH * HD];
    __shared__ __align__(16) float sk[2][2][CH * HD];
    __shared__ __align__(16) float sv[2][2][CH * HD];
    __shared__ __align__(16) float sb[2][2][CH];

    int tid = threadIdx.x;
    int pl  = tid >> 6;       // pair within block
    int i   = tid & 63;       // owned W row
    int bh0 = blockIdx.x * 2;
    int bh  = bh0 + pl;
    int bb  = bh >> 3, hh = bh & 7;

    ull W[32];
#pragma unroll
    for (int j = 0; j < 32; j++) W[j] = 0ull;

    auto load_chunk = [&](int buf, int t0) {
        int off = tid * 4;
        cp16(smem_u32(&sq[buf][0][off]), gq + ((size_t)(bh0    ) * SLEN + t0) * HD + off);
        cp16(smem_u32(&sq[buf][1][off]), gq + ((size_t)(bh0 + 1) * SLEN + t0) * HD + off);
        cp16(smem_u32(&sk[buf][0][off]), gk + ((size_t)(bh0    ) * SLEN + t0) * HD + off);
        cp16(smem_u32(&sk[buf][1][off]), gk + ((size_t)(bh0 + 1) * SLEN + t0) * HD + off);
        cp16(smem_u32(&sv[buf][0][off]), gv + ((size_t)(bh0    ) * SLEN + t0) * HD + off);
        cp16(smem_u32(&sv[buf][1][off]), gv + ((size_t)(bh0 + 1) * SLEN + t0) * HD + off);
        if (i < CH) cp4(smem_u32(&sb[buf][pl][i]), gb + (size_t)bh * SLEN + t0 + i);
    };

    load_chunk(0, 0);
    CP_COMMIT();
    int NCH = SLEN / CH;
    for (int c = 0; c < NCH; c++) {
        if (c + 1 < NCH) load_chunk((c + 1) & 1, (c + 1) * CH);
        CP_COMMIT();
        CP_WAIT1();
        __syncthreads();
        int buf = c & 1;
        const float* pq = &sq[buf][pl][0];
        const float* pk = &sk[buf][pl][0];
        const float* pv = &sv[buf][pl][0];
        const float* pb = &sb[buf][pl][0];
#pragma unroll
        for (int s = 0; s < CH; s++) {
            ull kc[32];
            const ull* k2 = (const ull*)(pk + s * HD);
#pragma unroll
            for (int j = 0; j < 32; j++) kc[j] = k2[j];
            ull a0 = 0, a1 = 0, a2 = 0, a3 = 0;
#pragma unroll
            for (int j = 0; j < 32; j += 4) {
                a0 = fma2(W[j],     kc[j],     a0);
                a1 = fma2(W[j + 1], kc[j + 1], a1);
                a2 = fma2(W[j + 2], kc[j + 2], a2);
                a3 = fma2(W[j + 3], kc[j + 3], a3);
            }
            float vold = (hsum2(a0) + hsum2(a1)) + (hsum2(a2) + hsum2(a3));
            float vi = pv[s * HD + i];
            float bt = pb[s];
            float u  = bt * (vi - vold);
            ull u2 = pack2(u, u);
#pragma unroll
            for (int j = 0; j < 32; j++) W[j] = fma2(u2, kc[j], W[j]);
            const ull* q2 = (const ull*)(pq + s * HD);
#pragma unroll
            for (int j = 0; j < 32; j++) kc[j] = q2[j];
            a0 = a1 = a2 = a3 = 0;
#pragma unroll
            for (int j = 0; j < 32; j += 4) {
                a0 = fma2(W[j],     kc[j],     a0);
                a1 = fma2(W[j + 1], kc[j + 1], a1);
                a2 = fma2(W[j + 2], kc[j + 2], a2);
                a3 = fma2(W[j + 3], kc[j + 3], a3);
            }
            float oi = (hsum2(a0) + hsum2(a1)) + (hsum2(a2) + hsum2(a3));
            int t = c * CH + s;
            go[((size_t)t * BSZ + bb) * IND + hh * HD + i] = __float2bfloat16_rn(oi);
        }
        __syncthreads();
    }
}

// ---------------- launch ----------------------------------------------------
extern "C" void kernel_launch(void* const* d_in, const int* in_sizes, int n_in,
                              void* d_out, int out_size)
{
    const float* x     = (const float*)d_in[0];
    const float* gam   = (const float*)d_in[1];
    const float* bet   = (const float*)d_in[2];
    const float* wslow = (const float*)d_in[3];
    const float* wout  = (const float*)d_in[4];

    __nv_bfloat16 *h, *qkvb, *o, *wsr, *wor;
    float *q, *k, *v, *be;
    cudaGetSymbolAddress((void**)&h,    g_h);
    cudaGetSymbolAddress((void**)&qkvb, g_qkvb);
    cudaGetSymbolAddress((void**)&q,    g_q);
    cudaGetSymbolAddress((void**)&k,    g_k);
    cudaGetSymbolAddress((void**)&v,    g_v);
    cudaGetSymbolAddress((void**)&be,   g_beta);
    cudaGetSymbolAddress((void**)&o,    g_o);
    cudaGetSymbolAddress((void**)&wsr,  g_wsr);
    cudaGetSymbolAddress((void**)&wor,  g_wor);

    round_w_kernel<<<592, 256>>>(wslow, wsr, IND * NQKV, wout, wor, IND * IND);

    ln_kernel<<<MROWS / 8, 256>>>(x, gam, bet, h);

    {
        dim3 grid((NQKV + BN - 1) / BN, MROWS / BM);
        gemm_bf16<false><<<grid, 256>>>(h, wsr, qkvb, nullptr, MROWS, NQKV, IND);
    }

    prep_kernel<<<MROWS * NH / 8, 256>>>(qkvb, q, k, v, be);

    recur_kernel<<<NPAIR / 2, 128>>>(q, k, v, be, o);

    {
        dim3 grid(IND / BN, MROWS / BM);
        gemm_bf16<true><<<grid, 256>>>(o, wor, d_out, x, MROWS, IND, IND);
    }
}

// round 14
// speedup vs baseline: 1.5728x; 1.0494x over previous
#include <cuda_runtime.h>
#include <cuda_bf16.h>
#include <cstdint>

typedef unsigned long long ull;

#define SLEN 1024
#define BSZ  32
#define IND  512
#define NH   8
#define HD   64
#define NQKV 1544              // H*(3*D+1)
#define MROWS (SLEN*BSZ)       // 32768
#define NPAIR (BSZ*NH)         // 256

// ---------------- scratch (device globals; no allocation allowed) ----------
__device__ __nv_bfloat16 g_h[(size_t)MROWS*IND];
__device__ __nv_bfloat16 g_qkvb[(size_t)MROWS*NQKV];
__device__ float g_q[(size_t)NPAIR*SLEN*HD];   // [bh][t][d] fp32 (recurrence precision)
__device__ float g_k[(size_t)NPAIR*SLEN*HD];
__device__ float g_v[(size_t)NPAIR*SLEN*HD];
__device__ float g_beta[(size_t)NPAIR*SLEN];
__device__ __nv_bfloat16 g_o[(size_t)MROWS*IND];
__device__ __nv_bfloat16 g_wsr[(size_t)IND*NQKV];
__device__ __nv_bfloat16 g_wor[(size_t)IND*IND];

// ---------------- helpers --------------------------------------------------
__device__ __forceinline__ uint32_t smem_u32(const void* p) {
    return (uint32_t)__cvta_generic_to_shared(p);
}
__device__ __forceinline__ void cp4(uint32_t d, const void* s) {
    asm volatile("cp.async.ca.shared.global [%0], [%1], 4;\n" :: "r"(d), "l"(s));
}
__device__ __forceinline__ void cp16(uint32_t d, const void* s) {
    asm volatile("cp.async.cg.shared.global [%0], [%1], 16;\n" :: "r"(d), "l"(s));
}
__device__ __forceinline__ void cp16z(uint32_t d, const void* s, int sz) {
    asm volatile("cp.async.cg.shared.global [%0], [%1], 16, %2;\n"
                 :: "r"(d), "l"(s), "r"(sz));
}
#define CP_COMMIT() asm volatile("cp.async.commit_group;\n" ::: "memory")
#define CP_WAIT1()  asm volatile("cp.async.wait_group 1;\n" ::: "memory")

__device__ __forceinline__ void ldsm_x4(uint32_t* r, uint32_t addr) {
    asm volatile("ldmatrix.sync.aligned.m8n8.x4.shared.b16 {%0,%1,%2,%3}, [%4];"
                 : "=r"(r[0]), "=r"(r[1]), "=r"(r[2]), "=r"(r[3]) : "r"(addr));
}
__device__ __forceinline__ void ldsm_x2t(uint32_t* r, uint32_t addr) {
    asm volatile("ldmatrix.sync.aligned.m8n8.x2.trans.shared.b16 {%0,%1}, [%2];"
                 : "=r"(r[0]), "=r"(r[1]) : "r"(addr));
}
__device__ __forceinline__ void mma_bf16(float* c, const uint32_t* a, const uint32_t* b) {
    asm volatile(
        "mma.sync.aligned.m16n8k16.row.col.f32.bf16.bf16.f32 "
        "{%0,%1,%2,%3},{%4,%5,%6,%7},{%8,%9},{%0,%1,%2,%3};\n"
        : "+f"(c[0]), "+f"(c[1]), "+f"(c[2]), "+f"(c[3])
        : "r"(a[0]), "r"(a[1]), "r"(a[2]), "r"(a[3]), "r"(b[0]), "r"(b[1]));
}

__device__ __forceinline__ ull fma2(ull a, ull b, ull c) {
    ull d; asm("fma.rn.f32x2 %0,%1,%2,%3;" : "=l"(d) : "l"(a), "l"(b), "l"(c)); return d;
}
__device__ __forceinline__ ull pack2(float x, float y) {
    ull r; asm("mov.b64 %0,{%1,%2};" : "=l"(r) : "f"(x), "f"(y)); return r;
}
__device__ __forceinline__ float hsum2(ull a) {
    float x, y; asm("mov.b64 {%0,%1},%2;" : "=f"(x), "=f"(y) : "l"(a)); return x + y;
}

// ---------------- weight rounding to bf16 (both matrices, one launch) ------
__global__ void round_w_kernel(const float* __restrict__ s1, __nv_bfloat16* __restrict__ d1, int n1,
                               const float* __restrict__ s2, __nv_bfloat16* __restrict__ d2, int n2) {
    int stride = gridDim.x * 256;
    for (int i = blockIdx.x * 256 + threadIdx.x; i < n1 + n2; i += stride) {
        if (i < n1) d1[i] = __float2bfloat16_rn(s1[i]);
        else        d2[i - n1] = __float2bfloat16_rn(s2[i - n1]);
    }
}

// ---------------- layernorm (fp32 in, bf16 out) ----------------------------
__global__ __launch_bounds__(256) void ln_kernel(
    const float* __restrict__ x, const float* __restrict__ gam,
    const float* __restrict__ bet, __nv_bfloat16* __restrict__ h)
{
    int row  = blockIdx.x * 8 + (threadIdx.x >> 5);
    int lane = threadIdx.x & 31;
    const float4* xr = (const float4*)(x + (size_t)row * IND);
    float4 v[4];
    float s = 0.f, s2 = 0.f;
#pragma unroll
    for (int i = 0; i < 4; i++) {
        v[i] = xr[lane + i * 32];
        s  += v[i].x + v[i].y + v[i].z + v[i].w;
        s2 += v[i].x*v[i].x + v[i].y*v[i].y + v[i].z*v[i].z + v[i].w*v[i].w;
    }
#pragma unroll
    for (int o = 16; o; o >>= 1) {
        s  += __shfl_xor_sync(0xffffffffu, s,  o);
        s2 += __shfl_xor_sync(0xffffffffu, s2, o);
    }
    float mu  = s * (1.f / IND);
    float var = s2 * (1.f / IND) - mu * mu;
    float ri  = rsqrtf(var + 1e-5f);
    const float4* gr = (const float4*)gam;
    const float4* br = (const float4*)bet;
    uint2* hr = (uint2*)(h + (size_t)row * IND);   // 4 bf16 per uint2
#pragma unroll
    for (int i = 0; i < 4; i++) {
        int c = lane + i * 32;
        float4 g4 = gr[c], b4 = br[c];
        __nv_bfloat162 lo = __floats2bfloat162_rn((v[i].x - mu) * ri * g4.x + b4.x,
                                                  (v[i].y - mu) * ri * g4.y + b4.y);
        __nv_bfloat162 hi = __floats2bfloat162_rn((v[i].z - mu) * ri * g4.z + b4.z,
                                                  (v[i].w - mu) * ri * g4.w + b4.w);
        uint2 o4;
        o4.x = *(uint32_t*)&lo;
        o4.y = *(uint32_t*)&hi;
        hr[c] = o4;
    }
}

// ---------------- bf16 GEMM: C[M,N] = A[M,K] @ B[K,N] (+R) -----------------
// BM=128, BN=128; 8 warps as 2m x 4n; warp tile 64m x 32n. Dynamic smem.
#define BM 128
#define BN 128
#define BK 32          // bf16 elements per K-tile (2 x k16 MMA steps)
#define ASTR 40        // bf16 per A row (80B = 5 chunks, gcd(5,8)=1 -> conflict-free)
#define BSTR 136       // bf16 per B row (272B = 17 chunks == 1 mod 8 -> conflict-free)
#define A_STAGE (BM*ASTR)
#define B_STAGE (BK*BSTR)
#define SMEM_BYTES (3*(A_STAGE+B_STAGE)*2)

template<bool RES>
__global__ __launch_bounds__(256) void gemm_bf16(
    const __nv_bfloat16* __restrict__ A, const __nv_bfloat16* __restrict__ B,
    void* __restrict__ Cout, const float* __restrict__ R,
    int M, int N, int K)
{
    extern __shared__ __align__(16) __nv_bfloat16 smem[];
    __nv_bfloat16* As = smem;                  // 3 stages of A
    __nv_bfloat16* Bs = smem + 3 * A_STAGE;    // 3 stages of B
    int tid = threadIdx.x, warp = tid >> 5, lane = tid & 31;
    int wm = warp >> 2, wn = warp & 3;          // 2 x 4 warp grid
    int m0 = blockIdx.y * BM, n0 = blockIdx.x * BN;
    int lr = lane & 7, sel = lane >> 3;         // ldmatrix address lanes

    float acc[4][4][4];
#pragma unroll
    for (int a = 0; a < 4; a++)
#pragma unroll
        for (int b = 0; b < 4; b++)
#pragma unroll
            for (int c = 0; c < 4; c++) acc[a][b][c] = 0.f;

    auto loadA = [&](int s, int k0) {
#pragma unroll
        for (int i = 0; i < 2; i++) {
            int idx = tid + i * 256;
            int row = idx >> 2, kc = (idx & 3) * 8;     // 8 bf16 = 16B chunk
            cp16(smem_u32(&As[s * A_STAGE + row * ASTR + kc]),
                 A + (size_t)(m0 + row) * K + k0 + kc);
        }
    };
    auto loadB = [&](int s, int k0) {
#pragma unroll
        for (int i = 0; i < 2; i++) {
            int idx = tid + i * 256;
            int row = idx >> 4, nc = (idx & 15) * 8;
            int col = n0 + nc;
            const __nv_bfloat16* src = (col < N) ? (B + (size_t)(k0 + row) * N + col) : B;
            cp16z(smem_u32(&Bs[s * B_STAGE + row * BSTR + nc]), src, (col < N) ? 16 : 0);
        }
    };

    int KT = K / BK;
    loadA(0, 0);  loadB(0, 0);  CP_COMMIT();
    loadA(1, BK); loadB(1, BK); CP_COMMIT();

    for (int kt = 0; kt < KT; kt++) {
        CP_WAIT1();
        __syncthreads();
        int kn = kt + 2;
        if (kn < KT) { loadA(kn % 3, kn * BK); loadB(kn % 3, kn * BK); }
        CP_COMMIT();

        int s = kt % 3;
#pragma unroll
        for (int kk = 0; kk < BK; kk += 16) {
            uint32_t af[4][4], bfr[4][2];
#pragma unroll
            for (int mi = 0; mi < 4; mi++) {
                int arow = wm * 64 + mi * 16 + ((sel & 1) << 3) + lr;
                int acol = kk + ((sel >> 1) << 3);
                ldsm_x4(af[mi], smem_u32(&As[s * A_STAGE + arow * ASTR + acol]));
            }
#pragma unroll
            for (int ni = 0; ni < 4; ni++) {
                int brow = kk + ((sel & 1) << 3) + lr;
                ldsm_x2t(bfr[ni], smem_u32(&Bs[s * B_STAGE + brow * BSTR + wn * 32 + ni * 8]));
            }
#pragma unroll
            for (int mi = 0; mi < 4; mi++)
#pragma unroll
                for (int ni = 0; ni < 4; ni++)
                    mma_bf16(acc[mi][ni], af[mi], bfr[ni]);
        }
    }

#pragma unroll
    for (int mi = 0; mi < 4; mi++)
#pragma unroll
        for (int ni = 0; ni < 4; ni++) {
            int row = m0 + wm * 64 + mi * 16 + (lane >> 2);
            int col = n0 + wn * 32 + ni * 8 + (lane & 3) * 2;
            if (col < N) {
                size_t i0 = (size_t)row * N + col;
                size_t i1 = (size_t)(row + 8) * N + col;
                const float* c4 = acc[mi][ni];
                if (RES) {
                    float* C = (float*)Cout;
                    float2 r0, r1;
                    r0.x = c4[0] + R[i0]; r0.y = c4[1] + R[i0 + 1];
                    r1.x = c4[2] + R[i1]; r1.y = c4[3] + R[i1 + 1];
                    *(float2*)(C + i0) = r0;
                    *(float2*)(C + i1) = r1;
                } else {
                    __nv_bfloat16* C = (__nv_bfloat16*)Cout;
                    __nv_bfloat162 p0 = __floats2bfloat162_rn(c4[0], c4[1]);
                    __nv_bfloat162 p1 = __floats2bfloat162_rn(c4[2], c4[3]);
                    *(__nv_bfloat162*)(C + i0) = p0;
                    *(__nv_bfloat162*)(C + i1) = p1;
                }
            }
        }
}

// ---------------- activation / transpose prep (bf16 in, fp32 out) ----------
__device__ __forceinline__ float elu1(float x) {
    return x > 0.f ? x + 1.f : __expf(x);
}

__global__ __launch_bounds__(256) void prep_kernel(
    const __nv_bfloat16* __restrict__ qkvb, float* __restrict__ q, float* __restrict__ k,
    float* __restrict__ v, float* __restrict__ be)
{
    int gw   = blockIdx.x * 8 + (threadIdx.x >> 5);
    int lane = threadIdx.x & 31;
    int h = gw & 7;
    int r = gw >> 3;          // r = t*32 + b
    int b = r & 31;
    int t = r >> 5;
    const __nv_bfloat16* base = qkvb + (size_t)r * NQKV + h * 193;
    int bh = b * NH + h;
    size_t od = ((size_t)bh * SLEN + t) * HD + lane;

    // q
    float q0 = elu1(__bfloat162float(base[lane]));
    float q1 = elu1(__bfloat162float(base[lane + 32]));
    float s = q0 + q1;
#pragma unroll
    for (int o = 16; o; o >>= 1) s += __shfl_xor_sync(0xffffffffu, s, o);
    float inv = 1.f / s;
    q[od] = q0 * inv; q[od + 32] = q1 * inv;
    // k
    float k0 = elu1(__bfloat162float(base[64 + lane]));
    float k1 = elu1(__bfloat162float(base[96 + lane]));
    s = k0 + k1;
#pragma unroll
    for (int o = 16; o; o >>= 1) s += __shfl_xor_sync(0xffffffffu, s, o);
    inv = 1.f / s;
    k[od] = k0 * inv; k[od + 32] = k1 * inv;
    // v
    v[od]      = __bfloat162float(base[128 + lane]);
    v[od + 32] = __bfloat162float(base[160 + lane]);
    // beta
    if (lane == 0) be[(size_t)bh * SLEN + t] = 1.f / (1.f + __expf(-__bfloat162float(base[192])));
}

// ---------------- delta-rule recurrence (fp32, bf16 output) -----------------
#define CH 8
__global__ __launch_bounds__(128) void recur_kernel(
    const float* __restrict__ gq, const float* __restrict__ gk,
    const float* __restrict__ gv, const float* __restrict__ gb,
    __nv_bfloat16* __restrict__ go)
{
    __shared__ __align__(16) float sq[2][2][CH * HD];
    __shared__ __align__(16) float sk[2][2][CH * HD];
    __shared__ __align__(16) float sv[2][2][CH * HD];
    __shared__ __align__(16) float sb[2][2][CH];

    int tid = threadIdx.x;
    int pl  = tid >> 6;       // pair within block
    int i   = tid & 63;       // owned W row
    int bh0 = blockIdx.x * 2;
    int bh  = bh0 + pl;
    int bb  = bh >> 3, hh = bh & 7;

    ull W[32];
#pragma unroll
    for (int j = 0; j < 32; j++) W[j] = 0ull;

    auto load_chunk = [&](int buf, int t0) {
        int off = tid * 4;
        cp16(smem_u32(&sq[buf][0][off]), gq + ((size_t)(bh0    ) * SLEN + t0) * HD + off);
        cp16(smem_u32(&sq[buf][1][off]), gq + ((size_t)(bh0 + 1) * SLEN + t0) * HD + off);
        cp16(smem_u32(&sk[buf][0][off]), gk + ((size_t)(bh0    ) * SLEN + t0) * HD + off);
        cp16(smem_u32(&sk[buf][1][off]), gk + ((size_t)(bh0 + 1) * SLEN + t0) * HD + off);
        cp16(smem_u32(&sv[buf][0][off]), gv + ((size_t)(bh0    ) * SLEN + t0) * HD + off);
        cp16(smem_u32(&sv[buf][1][off]), gv + ((size_t)(bh0 + 1) * SLEN + t0) * HD + off);
        if (i < CH) cp4(smem_u32(&sb[buf][pl][i]), gb + (size_t)bh * SLEN + t0 + i);
    };

    load_chunk(0, 0);
    CP_COMMIT();
    int NCH = SLEN / CH;
    for (int c = 0; c < NCH; c++) {
        if (c + 1 < NCH) load_chunk((c + 1) & 1, (c + 1) * CH);
        CP_COMMIT();
        CP_WAIT1();
        __syncthreads();
        int buf = c & 1;
        const float* pq = &sq[buf][pl][0];
        const float* pk = &sk[buf][pl][0];
        const float* pv = &sv[buf][pl][0];
        const float* pb = &sb[buf][pl][0];
#pragma unroll
        for (int s = 0; s < CH; s++) {
            ull kc[32];
            const ull* k2 = (const ull*)(pk + s * HD);
#pragma unroll
            for (int j = 0; j < 32; j++) kc[j] = k2[j];
            ull a0 = 0, a1 = 0, a2 = 0, a3 = 0;
#pragma unroll
            for (int j = 0; j < 32; j += 4) {
                a0 = fma2(W[j],     kc[j],     a0);
                a1 = fma2(W[j + 1], kc[j + 1], a1);
                a2 = fma2(W[j + 2], kc[j + 2], a2);
                a3 = fma2(W[j + 3], kc[j + 3], a3);
            }
            float vold = (hsum2(a0) + hsum2(a1)) + (hsum2(a2) + hsum2(a3));
            float vi = pv[s * HD + i];
            float bt = pb[s];
            float u  = bt * (vi - vold);
            ull u2 = pack2(u, u);
#pragma unroll
            for (int j = 0; j < 32; j++) W[j] = fma2(u2, kc[j], W[j]);
            const ull* q2 = (const ull*)(pq + s * HD);
#pragma unroll
            for (int j = 0; j < 32; j++) kc[j] = q2[j];
            a0 = a1 = a2 = a3 = 0;
#pragma unroll
            for (int j = 0; j < 32; j += 4) {
                a0 = fma2(W[j],     kc[j],     a0);
                a1 = fma2(W[j + 1], kc[j + 1], a1);
                a2 = fma2(W[j + 2], kc[j + 2], a2);
                a3 = fma2(W[j + 3], kc[j + 3], a3);
            }
            float oi = (hsum2(a0) + hsum2(a1)) + (hsum2(a2) + hsum2(a3));
            int t = c * CH + s;
            go[((size_t)t * BSZ + bb) * IND + hh * HD + i] = __float2bfloat16_rn(oi);
        }
        __syncthreads();
    }
}

// ---------------- launch ----------------------------------------------------
extern "C" void kernel_launch(void* const* d_in, const int* in_sizes, int n_in,
                              void* d_out, int out_size)
{
    const float* x     = (const float*)d_in[0];
    const float* gam   = (const float*)d_in[1];
    const float* bet   = (const float*)d_in[2];
    const float* wslow = (const float*)d_in[3];
    const float* wout  = (const float*)d_in[4];

    __nv_bfloat16 *h, *qkvb, *o, *wsr, *wor;
    float *q, *k, *v, *be;
    cudaGetSymbolAddress((void**)&h,    g_h);
    cudaGetSymbolAddress((void**)&qkvb, g_qkvb);
    cudaGetSymbolAddress((void**)&q,    g_q);
    cudaGetSymbolAddress((void**)&k,    g_k);
    cudaGetSymbolAddress((void**)&v,    g_v);
    cudaGetSymbolAddress((void**)&be,   g_beta);
    cudaGetSymbolAddress((void**)&o,    g_o);
    cudaGetSymbolAddress((void**)&wsr,  g_wsr);
    cudaGetSymbolAddress((void**)&wor,  g_wor);

    cudaFuncSetAttribute(gemm_bf16<false>, cudaFuncAttributeMaxDynamicSharedMemorySize, SMEM_BYTES);
    cudaFuncSetAttribute(gemm_bf16<true>,  cudaFuncAttributeMaxDynamicSharedMemorySize, SMEM_BYTES);

    round_w_kernel<<<592, 256>>>(wslow, wsr, IND * NQKV, wout, wor, IND * IND);

    ln_kernel<<<MROWS / 8, 256>>>(x, gam, bet, h);

    {
        dim3 grid((NQKV + BN - 1) / BN, MROWS / BM);
        gemm_bf16<false><<<grid, 256, SMEM_BYTES>>>(h, wsr, qkvb, nullptr, MROWS, NQKV, IND);
    }

    prep_kernel<<<MROWS * NH / 8, 256>>>(qkvb, q, k, v, be);

    recur_kernel<<<NPAIR / 2, 128>>>(q, k, v, be, o);

    {
        dim3 grid(IND / BN, MROWS / BM);
        gemm_bf16<true><<<grid, 256, SMEM_BYTES>>>(o, wor, d_out, x, MROWS, IND, IND);
    }
}